// round 15
// baseline (speedup 1.0000x reference)
#include <cuda_runtime.h>
#include <cuda_fp16.h>
#include <cstdint>

#define D_MODEL 2048
#define KV_DIM  512
#define BATCH   2
#define SEQ     2048
#define MTOK    4096
#define HEADS   32
#define HDIM    64

// Scratch (device globals: no allocations allowed) — fp16 data path
__device__ __half g_X [(size_t)MTOK * D_MODEL];
__device__ __half g_Wq[(size_t)D_MODEL * D_MODEL];
__device__ __half g_Wk[(size_t)D_MODEL * KV_DIM];
__device__ __half g_Wv[(size_t)D_MODEL * KV_DIM];
__device__ __half g_Wo[(size_t)D_MODEL * D_MODEL];
__device__ __half g_Q [(size_t)MTOK * D_MODEL];   // pre-scaled by 0.125*log2e
__device__ __half g_K [(size_t)MTOK * KV_DIM];
__device__ __half g_V [(size_t)MTOK * KV_DIM];
__device__ __half g_C [(size_t)MTOK * D_MODEL];

// ---------------------------------------------------------------------------
// helpers
// ---------------------------------------------------------------------------
__device__ __forceinline__ float ex2(float x) {
    float r;
    asm("ex2.approx.f32 %0, %1;" : "=f"(r) : "f"(x));
    return r;
}
__device__ __forceinline__ unsigned ex2h2(unsigned x) {
    unsigned r;
    asm("ex2.approx.f16x2 %0, %1;" : "=r"(r) : "r"(x));
    return r;
}
__device__ __forceinline__ unsigned packh2(float a, float b) {
    __half2 h = __floats2half2_rn(a, b);
    return *reinterpret_cast<unsigned*>(&h);
}
__device__ __forceinline__ float2 unpackh2(unsigned u) {
    return __half22float2(*reinterpret_cast<__half2*>(&u));
}
__device__ __forceinline__ void mma16(float* d, const unsigned* a, const unsigned* b) {
    asm volatile(
        "mma.sync.aligned.m16n8k16.row.col.f32.f16.f16.f32 "
        "{%0,%1,%2,%3},{%4,%5,%6,%7},{%8,%9},{%0,%1,%2,%3};"
        : "+f"(d[0]), "+f"(d[1]), "+f"(d[2]), "+f"(d[3])
        : "r"(a[0]), "r"(a[1]), "r"(a[2]), "r"(a[3]), "r"(b[0]), "r"(b[1]));
}
__device__ __forceinline__ void ldsm4(unsigned* r, uint32_t a) {
    asm volatile("ldmatrix.sync.aligned.m8n8.x4.shared.b16 {%0,%1,%2,%3}, [%4];"
                 : "=r"(r[0]), "=r"(r[1]), "=r"(r[2]), "=r"(r[3]) : "r"(a));
}
__device__ __forceinline__ void ldsm4t(unsigned* r, uint32_t a) {
    asm volatile("ldmatrix.sync.aligned.m8n8.x4.trans.shared.b16 {%0,%1,%2,%3}, [%4];"
                 : "=r"(r[0]), "=r"(r[1]), "=r"(r[2]), "=r"(r[3]) : "r"(a));
}
__device__ __forceinline__ void cpa16(uint32_t dst, const void* src) {
    asm volatile("cp.async.cg.shared.global [%0], [%1], 16;" :: "r"(dst), "l"(src));
}
__device__ __forceinline__ void cpa_commit() {
    asm volatile("cp.async.commit_group;");
}
template <int N>
__device__ __forceinline__ void cpa_wait() {
    asm volatile("cp.async.wait_group %0;" :: "n"(N));
}

// ---------------------------------------------------------------------------
// Fused pre-pass: fp32 -> fp16 for x + all 4 weights in one launch.
// ---------------------------------------------------------------------------
#define SEG0 (MTOK * D_MODEL / 4)
#define SEG1 (SEG0 + D_MODEL * D_MODEL / 4)
#define SEG2 (SEG1 + D_MODEL * KV_DIM / 4)
#define SEG3 (SEG2 + D_MODEL * KV_DIM / 4)
#define SEG4 (SEG3 + D_MODEL * D_MODEL / 4)

__global__ __launch_bounds__(256)
void cvt_all(const float4* __restrict__ x,  const float4* __restrict__ wq,
             const float4* __restrict__ wk, const float4* __restrict__ wv,
             const float4* __restrict__ wo,
             uint2* __restrict__ ox,  uint2* __restrict__ owq,
             uint2* __restrict__ owk, uint2* __restrict__ owv,
             uint2* __restrict__ owo)
{
    int i = blockIdx.x * 256 + threadIdx.x;
    const float4* src; uint2* dst; int off;
    if (i < SEG0)      { src = x;  dst = ox;  off = i; }
    else if (i < SEG1) { src = wq; dst = owq; off = i - SEG0; }
    else if (i < SEG2) { src = wk; dst = owk; off = i - SEG1; }
    else if (i < SEG3) { src = wv; dst = owv; off = i - SEG2; }
    else               { src = wo; dst = owo; off = i - SEG3; }
    float4 v = src[off];
    uint2 u;
    u.x = packh2(v.x, v.y);
    u.y = packh2(v.z, v.w);
    dst[off] = u;
}

// ---------------------------------------------------------------------------
// fp16 GEMM (fp32 accum): C[M,N] = (A[M,K] @ B[K,N] + bias) * outScale.
// CTA tile 128(M) x 64(N): fine grain kills per-SM load imbalance.
// K-step 32, 3-stage ring, single barrier per stage, 4 warps x (64x32).
// ---------------------------------------------------------------------------
#define A_STR 80
#define B_STR 144
#define A_ST  (128 * A_STR)     // 10240 B
#define B_ST  (32 * B_STR)      //  4608 B
#define GSTAGES 3
#define GEMM_SMEM (GSTAGES * (A_ST + B_ST))    // 44544 B

__device__ __forceinline__ void gemm_core(
    const __half* __restrict__ A, const __half* __restrict__ B,
    const float* __restrict__ bias, float* __restrict__ Cf, __half* __restrict__ Ch,
    int N, int K, int colb, int by, float outScale)
{
    extern __shared__ char smg[];
    const uint32_t su = (uint32_t)__cvta_generic_to_shared(smg);

    const int tid  = threadIdx.x;
    const int lane = tid & 31;
    const int wid  = tid >> 5;
    const int wm = (wid & 1) * 64;       // M offset 0/64
    const int wn = (wid >> 1) * 32;      // N offset 0/32
    const int g  = lane >> 2;
    const int tg = lane & 3;
    const int lrow8 = (lane & 7) + ((lane >> 3) & 1) * 8;
    const int lhi   = lane >> 4;

    float acc[4][4][4];
    #pragma unroll
    for (int mt = 0; mt < 4; mt++)
        #pragma unroll
        for (int nt = 0; nt < 4; nt++)
            #pragma unroll
            for (int i = 0; i < 4; i++) acc[mt][nt][i] = 0.f;

    auto issue = [&](int stg) {
        const int st = stg % GSTAGES;
        const int k0 = stg * 32;
        const uint32_t ab = su + st * (A_ST + B_ST);
        const uint32_t bb = ab + A_ST;
        #pragma unroll
        for (int p = 0; p < 4; p++) {       // A 128x32 (512 x 16B)
            int idx = p * 128 + tid;
            int r = idx >> 2, c = idx & 3;
            cpa16(ab + r * A_STR + c * 16, A + (size_t)(by * 128 + r) * K + k0 + c * 8);
        }
        #pragma unroll
        for (int p = 0; p < 2; p++) {       // B 32x64 (256 x 16B)
            int idx = p * 128 + tid;
            int r = idx >> 3, c = idx & 7;
            cpa16(bb + r * B_STR + c * 16, B + (size_t)(k0 + r) * N + colb + c * 8);
        }
        cpa_commit();
    };

    const int nsteps = K / 32;
    issue(0); issue(1);

    for (int s = 0; s < nsteps; s++) {
        if (s + 1 < nsteps) cpa_wait<1>();
        else                cpa_wait<0>();
        __syncthreads();
        if (s + 2 < nsteps) issue(s + 2);

        const uint32_t ab = su + (s % GSTAGES) * (A_ST + B_ST);
        const uint32_t bb = ab + A_ST;

        #pragma unroll
        for (int kk = 0; kk < 32; kk += 16) {
            unsigned af[4][4], bf[2][4];
            #pragma unroll
            for (int mt = 0; mt < 4; mt++)
                ldsm4(af[mt], ab + (wm + mt * 16 + lrow8) * A_STR
                                 + ((kk >> 3) + lhi) * 16);
            #pragma unroll
            for (int ntp = 0; ntp < 2; ntp++)
                ldsm4t(bf[ntp], bb + (kk + lrow8) * B_STR
                                   + (((wn + ntp * 16) >> 3) + lhi) * 16);
            #pragma unroll
            for (int mt = 0; mt < 4; mt++)
                #pragma unroll
                for (int ntp = 0; ntp < 2; ntp++) {
                    mma16(acc[mt][2 * ntp],     af[mt], bf[ntp] + 0);
                    mma16(acc[mt][2 * ntp + 1], af[mt], bf[ntp] + 2);
                }
        }
    }

    #pragma unroll
    for (int mt = 0; mt < 4; mt++) {
        const int row = by * 128 + wm + mt * 16 + g;
        #pragma unroll
        for (int nt = 0; nt < 4; nt++) {
            const int col = colb + wn + nt * 8 + tg * 2;
            const float b0 = bias[col], b1 = bias[col + 1];
            float v0 = (acc[mt][nt][0] + b0) * outScale;
            float v1 = (acc[mt][nt][1] + b1) * outScale;
            float v2 = (acc[mt][nt][2] + b0) * outScale;
            float v3 = (acc[mt][nt][3] + b1) * outScale;
            if (Ch) {
                *(unsigned*)(Ch + (size_t)row * N + col)       = packh2(v0, v1);
                *(unsigned*)(Ch + (size_t)(row + 8) * N + col) = packh2(v2, v3);
            } else {
                *(float2*)(Cf + (size_t)row * N + col)       = make_float2(v0, v1);
                *(float2*)(Cf + (size_t)(row + 8) * N + col) = make_float2(v2, v3);
            }
        }
    }
}

#define QSCALE (0.125f * 1.4426950408889634f)

// Fused QKV projection over 64-wide N tiles:
// bx 0..31 -> Wq (scaled), 32..39 -> Wk, 40..47 -> Wv
__global__ __launch_bounds__(128, 3)
void gemm_qkv(const __half* __restrict__ x,
              const __half* __restrict__ Wq, const float* __restrict__ bq,
              const __half* __restrict__ Wk, const float* __restrict__ bk,
              const __half* __restrict__ Wv, const float* __restrict__ bv,
              __half* __restrict__ Qo, __half* __restrict__ Ko, __half* __restrict__ Vo)
{
    const int bx = blockIdx.x;
    const __half* B; const float* bias; __half* C; int N, colb; float sc;
    if (bx < 32)      { B = Wq; bias = bq; C = Qo; N = D_MODEL; colb = bx * 64; sc = QSCALE; }
    else if (bx < 40) { B = Wk; bias = bk; C = Ko; N = KV_DIM;  colb = (bx - 32) * 64; sc = 1.f; }
    else              { B = Wv; bias = bv; C = Vo; N = KV_DIM;  colb = (bx - 40) * 64; sc = 1.f; }
    gemm_core(x, B, bias, nullptr, C, N, D_MODEL, colb, blockIdx.y, sc);
}

__global__ __launch_bounds__(128, 3)
void gemm_o(const __half* __restrict__ A, const __half* __restrict__ B,
            const float* __restrict__ bias, float* __restrict__ C)
{
    gemm_core(A, B, bias, C, nullptr, D_MODEL, D_MODEL, blockIdx.x * 64, blockIdx.y, 1.f);
}

// ---------------------------------------------------------------------------
// Flash attention, fp16 MMA (fp32 accum). 64-query CTAs: 4 warps x 16 rows,
// 128 threads, 3 CTAs/SM. 3-stage KV ring, single barrier per tile;
// P via ex2.approx.f16x2.
// ---------------------------------------------------------------------------
#define KV_STR   144
#define KV_TILE  (64 * KV_STR)               // 9216 B
#define KV_STAGE (2 * KV_TILE)               // 18432 B
#define ASTAGES  3
#define QROWS_A  64
#define Q_OFF    (ASTAGES * KV_STAGE)        // 55296
#define ATTN_SMEM (Q_OFF + QROWS_A * KV_STR) // 64512 B
#define NKT    (SEQ / 64)

__global__ __launch_bounds__(128, 3)
void attn_f16(const __half* __restrict__ Q, const __half* __restrict__ K,
              const __half* __restrict__ V, __half* __restrict__ C)
{
    extern __shared__ char sma[];
    const uint32_t su = (uint32_t)__cvta_generic_to_shared(sma);
    const uint32_t qOff = su + Q_OFF;

    const int tid  = threadIdx.x;
    const int lane = tid & 31;
    const int wid  = tid >> 5;
    const int g    = lane >> 2;
    const int tg   = lane & 3;
    const int r0   = wid * 16;
    const int lrow8 = (lane & 7) + ((lane >> 3) & 1) * 8;
    const int lhi   = lane >> 4;

    const int qt = blockIdx.x;
    const int h  = blockIdx.y;
    const int b  = blockIdx.z;
    const int hkv = h >> 2;

    auto issueKV = [&](int kt) {
        const int st = kt % ASTAGES;
        #pragma unroll
        for (int p = 0; p < 8; p++) {
            int idx = p * 128 + tid;
            int sel = idx >> 9;
            int jj = (idx >> 3) & 63;
            int c  = idx & 7;
            const __half* src = (sel ? V : K)
                + (size_t)(b * SEQ + kt * 64 + jj) * KV_DIM + hkv * HDIM + c * 8;
            cpa16(su + st * KV_STAGE + sel * KV_TILE + jj * KV_STR + c * 16, src);
        }
        cpa_commit();
    };

    // Q tile via cp.async (pre-scaled fp16; 64 rows x 8 chunks)
    {
        #pragma unroll
        for (int p = 0; p < 4; p++) {
            int idx = p * 128 + tid;
            int r = idx >> 3, c = idx & 7;
            cpa16(qOff + r * KV_STR + c * 16,
                  Q + (size_t)(b * SEQ + qt * QROWS_A + r) * D_MODEL + h * HDIM + c * 8);
        }
        cpa_commit();
    }
    issueKV(0); issueKV(1);

    unsigned aQ[4][4];
    float o[8][4];
    #pragma unroll
    for (int nt = 0; nt < 8; nt++)
        #pragma unroll
        for (int i = 0; i < 4; i++) o[nt][i] = 0.f;
    float m0 = -1e30f, m1 = -1e30f, l0 = 0.f, l1 = 0.f;

    for (int kt = 0; kt < NKT; kt++) {
        if (kt + 1 < NKT) cpa_wait<1>();
        else              cpa_wait<0>();
        __syncthreads();
        if (kt + 2 < NKT) issueKV(kt + 2);

        if (kt == 0) {
            #pragma unroll
            for (int kki = 0; kki < 4; kki++)
                ldsm4(aQ[kki], qOff + (r0 + lrow8) * KV_STR + (kki * 2 + lhi) * 16);
        }

        const uint32_t kb = su + (kt % ASTAGES) * KV_STAGE;
        const uint32_t vb = kb + KV_TILE;

        // S = Q @ K^T (log2-scaled, fp32 accum)
        float s[8][4];
        #pragma unroll
        for (int nt = 0; nt < 8; nt++)
            #pragma unroll
            for (int i = 0; i < 4; i++) s[nt][i] = 0.f;

        #pragma unroll
        for (int kki = 0; kki < 4; kki++) {
            #pragma unroll
            for (int ntp = 0; ntp < 4; ntp++) {
                unsigned bK[4];
                ldsm4(bK, kb + (ntp * 16 + (lane & 7) + lhi * 8) * KV_STR
                             + (kki * 2 + ((lane >> 3) & 1)) * 16);
                mma16(s[2 * ntp],     aQ[kki], bK + 0);
                mma16(s[2 * ntp + 1], aQ[kki], bK + 2);
            }
        }

        // Online softmax (exp2 domain, f16x2 MUFU); P kept packed
        unsigned ph[8][2];
        {
            float tm0 = -1e30f, tm1 = -1e30f;
            #pragma unroll
            for (int nt = 0; nt < 8; nt++) {
                tm0 = fmaxf(tm0, fmaxf(s[nt][0], s[nt][1]));
                tm1 = fmaxf(tm1, fmaxf(s[nt][2], s[nt][3]));
            }
            tm0 = fmaxf(tm0, __shfl_xor_sync(0xffffffffu, tm0, 1));
            tm0 = fmaxf(tm0, __shfl_xor_sync(0xffffffffu, tm0, 2));
            tm1 = fmaxf(tm1, __shfl_xor_sync(0xffffffffu, tm1, 1));
            tm1 = fmaxf(tm1, __shfl_xor_sync(0xffffffffu, tm1, 2));

            float nm0 = fmaxf(m0, tm0), nm1 = fmaxf(m1, tm1);
            float c0 = ex2(m0 - nm0), c1 = ex2(m1 - nm1);
            m0 = nm0; m1 = nm1;

            float rs0 = 0.f, rs1 = 0.f;
            #pragma unroll
            for (int nt = 0; nt < 8; nt++) {
                unsigned p01 = ex2h2(packh2(s[nt][0] - nm0, s[nt][1] - nm0));
                unsigned p23 = ex2h2(packh2(s[nt][2] - nm1, s[nt][3] - nm1));
                ph[nt][0] = p01;
                ph[nt][1] = p23;
                float2 f01 = unpackh2(p01);
                float2 f23 = unpackh2(p23);
                rs0 += f01.x + f01.y;
                rs1 += f23.x + f23.y;
                o[nt][0] *= c0; o[nt][1] *= c0;
                o[nt][2] *= c1; o[nt][3] *= c1;
            }
            rs0 += __shfl_xor_sync(0xffffffffu, rs0, 1);
            rs0 += __shfl_xor_sync(0xffffffffu, rs0, 2);
            rs1 += __shfl_xor_sync(0xffffffffu, rs1, 1);
            rs1 += __shfl_xor_sync(0xffffffffu, rs1, 2);
            l0 = l0 * c0 + rs0;
            l1 = l1 * c1 + rs1;
        }

        // O += P @ V (fp32 accum)
        #pragma unroll
        for (int j = 0; j < 4; j++) {
            unsigned aP[4];
            aP[0] = ph[2 * j][0];     aP[1] = ph[2 * j][1];
            aP[2] = ph[2 * j + 1][0]; aP[3] = ph[2 * j + 1][1];
            #pragma unroll
            for (int ntp = 0; ntp < 4; ntp++) {
                unsigned bV[4];
                ldsm4t(bV, vb + (j * 16 + lrow8) * KV_STR + (ntp * 2 + lhi) * 16);
                mma16(o[2 * ntp],     aP, bV + 0);
                mma16(o[2 * ntp + 1], aP, bV + 2);
            }
        }
    }

    // Normalize, write context fp16
    {
        const float i0 = 1.f / l0, i1 = 1.f / l1;
        #pragma unroll
        for (int nt = 0; nt < 8; nt++) {
            const size_t row = (size_t)(b * SEQ + qt * QROWS_A + r0 + g);
            const int col = h * HDIM + nt * 8 + tg * 2;
            *(unsigned*)(C + row * D_MODEL + col) =
                packh2(o[nt][0] * i0, o[nt][1] * i0);
            *(unsigned*)(C + (row + 8) * D_MODEL + col) =
                packh2(o[nt][2] * i1, o[nt][3] * i1);
        }
    }
}

// ---------------------------------------------------------------------------
// Launch
// ---------------------------------------------------------------------------
extern "C" void kernel_launch(void* const* d_in, const int* in_sizes, int n_in,
                              void* d_out, int out_size)
{
    const float* x  = (const float*)d_in[0];
    const float* Wq = (const float*)d_in[1];
    const float* bq = (const float*)d_in[2];
    const float* Wk = (const float*)d_in[3];
    const float* bk = (const float*)d_in[4];
    const float* Wv = (const float*)d_in[5];
    const float* bv = (const float*)d_in[6];
    const float* Wo = (const float*)d_in[7];
    const float* bo = (const float*)d_in[8];
    float* out = (float*)d_out;

    __half *pX, *pWq, *pWk, *pWv, *pWo, *pQ, *pK, *pV, *pC;
    cudaGetSymbolAddress((void**)&pX, g_X);
    cudaGetSymbolAddress((void**)&pWq, g_Wq);
    cudaGetSymbolAddress((void**)&pWk, g_Wk);
    cudaGetSymbolAddress((void**)&pWv, g_Wv);
    cudaGetSymbolAddress((void**)&pWo, g_Wo);
    cudaGetSymbolAddress((void**)&pQ, g_Q);
    cudaGetSymbolAddress((void**)&pK, g_K);
    cudaGetSymbolAddress((void**)&pV, g_V);
    cudaGetSymbolAddress((void**)&pC, g_C);

    cudaFuncSetAttribute(gemm_qkv, cudaFuncAttributeMaxDynamicSharedMemorySize, GEMM_SMEM);
    cudaFuncSetAttribute(gemm_o,   cudaFuncAttributeMaxDynamicSharedMemorySize, GEMM_SMEM);
    cudaFuncSetAttribute(attn_f16, cudaFuncAttributeMaxDynamicSharedMemorySize, ATTN_SMEM);

    // Fused pre-pass: fp32 -> fp16 for all inputs
    cvt_all<<<SEG4 / 256, 256>>>((const float4*)x,  (const float4*)Wq,
                                 (const float4*)Wk, (const float4*)Wv,
                                 (const float4*)Wo,
                                 (uint2*)pX, (uint2*)pWq, (uint2*)pWk,
                                 (uint2*)pWv, (uint2*)pWo);

    // Fused QKV projection: 48 N-tiles (64 wide) x 32 M-tiles
    gemm_qkv<<<dim3(48, MTOK / 128), 128, GEMM_SMEM>>>(
        pX, pWq, bq, pWk, bk, pWv, bv, pQ, pK, pV);

    // Attention (64-query tiles, 3 CTAs/SM)
    attn_f16<<<dim3(SEQ / QROWS_A, HEADS, BATCH), 128, ATTN_SMEM>>>(pQ, pK, pV, pC);

    // Output projection: 32 N-tiles (64 wide) x 32 M-tiles
    gemm_o<<<dim3(D_MODEL / 64, MTOK / 128), 128, GEMM_SMEM>>>(pC, pWo, bo, out);
}

// round 16
// speedup vs baseline: 1.0008x; 1.0008x over previous
#include <cuda_runtime.h>
#include <cuda_fp16.h>
#include <cstdint>

#define D_MODEL 2048
#define KV_DIM  512
#define BATCH   2
#define SEQ     2048
#define MTOK    4096
#define HEADS   32
#define HDIM    64

// Scratch (device globals: no allocations allowed) — fp16 data path
__device__ __half g_X [(size_t)MTOK * D_MODEL];
__device__ __half g_Wq[(size_t)D_MODEL * D_MODEL];
__device__ __half g_Wk[(size_t)D_MODEL * KV_DIM];
__device__ __half g_Wv[(size_t)D_MODEL * KV_DIM];
__device__ __half g_Wo[(size_t)D_MODEL * D_MODEL];
__device__ __half g_Q [(size_t)MTOK * D_MODEL];   // pre-scaled by 0.125*log2e
__device__ __half g_K [(size_t)MTOK * KV_DIM];
__device__ __half g_V [(size_t)MTOK * KV_DIM];
__device__ __half g_C [(size_t)MTOK * D_MODEL];

// ---------------------------------------------------------------------------
// helpers
// ---------------------------------------------------------------------------
__device__ __forceinline__ float ex2(float x) {
    float r;
    asm("ex2.approx.f32 %0, %1;" : "=f"(r) : "f"(x));
    return r;
}
__device__ __forceinline__ unsigned ex2h2(unsigned x) {
    unsigned r;
    asm("ex2.approx.f16x2 %0, %1;" : "=r"(r) : "r"(x));
    return r;
}
__device__ __forceinline__ unsigned packh2(float a, float b) {
    __half2 h = __floats2half2_rn(a, b);
    return *reinterpret_cast<unsigned*>(&h);
}
__device__ __forceinline__ float2 unpackh2(unsigned u) {
    return __half22float2(*reinterpret_cast<__half2*>(&u));
}
__device__ __forceinline__ void mma16(float* d, const unsigned* a, const unsigned* b) {
    asm volatile(
        "mma.sync.aligned.m16n8k16.row.col.f32.f16.f16.f32 "
        "{%0,%1,%2,%3},{%4,%5,%6,%7},{%8,%9},{%0,%1,%2,%3};"
        : "+f"(d[0]), "+f"(d[1]), "+f"(d[2]), "+f"(d[3])
        : "r"(a[0]), "r"(a[1]), "r"(a[2]), "r"(a[3]), "r"(b[0]), "r"(b[1]));
}
__device__ __forceinline__ void ldsm4(unsigned* r, uint32_t a) {
    asm volatile("ldmatrix.sync.aligned.m8n8.x4.shared.b16 {%0,%1,%2,%3}, [%4];"
                 : "=r"(r[0]), "=r"(r[1]), "=r"(r[2]), "=r"(r[3]) : "r"(a));
}
__device__ __forceinline__ void ldsm4t(unsigned* r, uint32_t a) {
    asm volatile("ldmatrix.sync.aligned.m8n8.x4.trans.shared.b16 {%0,%1,%2,%3}, [%4];"
                 : "=r"(r[0]), "=r"(r[1]), "=r"(r[2]), "=r"(r[3]) : "r"(a));
}
__device__ __forceinline__ void cpa16(uint32_t dst, const void* src) {
    asm volatile("cp.async.cg.shared.global [%0], [%1], 16;" :: "r"(dst), "l"(src));
}
__device__ __forceinline__ void cpa_commit() {
    asm volatile("cp.async.commit_group;");
}
template <int N>
__device__ __forceinline__ void cpa_wait() {
    asm volatile("cp.async.wait_group %0;" :: "n"(N));
}

// ---------------------------------------------------------------------------
// Fused pre-pass: fp32 -> fp16 for x + all 4 weights in one launch.
// ---------------------------------------------------------------------------
#define SEG0 (MTOK * D_MODEL / 4)
#define SEG1 (SEG0 + D_MODEL * D_MODEL / 4)
#define SEG2 (SEG1 + D_MODEL * KV_DIM / 4)
#define SEG3 (SEG2 + D_MODEL * KV_DIM / 4)
#define SEG4 (SEG3 + D_MODEL * D_MODEL / 4)

__global__ __launch_bounds__(256)
void cvt_all(const float4* __restrict__ x,  const float4* __restrict__ wq,
             const float4* __restrict__ wk, const float4* __restrict__ wv,
             const float4* __restrict__ wo,
             uint2* __restrict__ ox,  uint2* __restrict__ owq,
             uint2* __restrict__ owk, uint2* __restrict__ owv,
             uint2* __restrict__ owo)
{
    int i = blockIdx.x * 256 + threadIdx.x;
    const float4* src; uint2* dst; int off;
    if (i < SEG0)      { src = x;  dst = ox;  off = i; }
    else if (i < SEG1) { src = wq; dst = owq; off = i - SEG0; }
    else if (i < SEG2) { src = wk; dst = owk; off = i - SEG1; }
    else if (i < SEG3) { src = wv; dst = owv; off = i - SEG2; }
    else               { src = wo; dst = owo; off = i - SEG3; }
    float4 v = src[off];
    uint2 u;
    u.x = packh2(v.x, v.y);
    u.y = packh2(v.z, v.w);
    dst[off] = u;
}

// ---------------------------------------------------------------------------
// fp16 GEMM (fp32 accum), templated N-tile width (128 for qkv: A reuse;
// 64 for gemm_o: wave balance). CTA 128(M) x NT(N), K-step 32, 3-stage ring,
// single barrier per stage, 4 warps, LDSM operands.
// ---------------------------------------------------------------------------
#define A_STR 80
#define A_ST  (128 * A_STR)     // 10240 B
#define GSTAGES 3

template <int NT>
__device__ __forceinline__ void gemm_core(
    const __half* __restrict__ A, const __half* __restrict__ B,
    const float* __restrict__ bias, float* __restrict__ Cf, __half* __restrict__ Ch,
    int N, int K, int colb, int by, float outScale)
{
    constexpr int B_STR = 2 * NT + 16;        // 272 (NT=128) / 144 (NT=64)
    constexpr int B_ST  = 32 * B_STR;
    constexpr int NTP   = NT / 32;            // B ldsm tiles per warp (4 / 2)
    constexpr int WN    = NT / 2;             // warp N span (64 / 32)

    extern __shared__ char smg[];
    const uint32_t su = (uint32_t)__cvta_generic_to_shared(smg);

    const int tid  = threadIdx.x;
    const int lane = tid & 31;
    const int wid  = tid >> 5;
    const int wm = (wid & 1) * 64;
    const int wn = (wid >> 1) * WN;
    const int g  = lane >> 2;
    const int tg = lane & 3;
    const int lrow8 = (lane & 7) + ((lane >> 3) & 1) * 8;
    const int lhi   = lane >> 4;

    float acc[4][2 * NTP][4];
    #pragma unroll
    for (int mt = 0; mt < 4; mt++)
        #pragma unroll
        for (int nt = 0; nt < 2 * NTP; nt++)
            #pragma unroll
            for (int i = 0; i < 4; i++) acc[mt][nt][i] = 0.f;

    auto issue = [&](int stg) {
        const int st = stg % GSTAGES;
        const int k0 = stg * 32;
        const uint32_t ab = su + st * (A_ST + B_ST);
        const uint32_t bb = ab + A_ST;
        #pragma unroll
        for (int p = 0; p < 4; p++) {          // A 128x32 (512 x 16B)
            int idx = p * 128 + tid;
            int r = idx >> 2, c = idx & 3;
            cpa16(ab + r * A_STR + c * 16, A + (size_t)(by * 128 + r) * K + k0 + c * 8);
        }
        #pragma unroll
        for (int p = 0; p < NT / 32; p++) {    // B 32xNT (NT*2 x 16B)
            int idx = p * 128 + tid;
            int r = idx / (NT / 8), c = idx % (NT / 8);
            cpa16(bb + r * B_STR + c * 16, B + (size_t)(k0 + r) * N + colb + c * 8);
        }
        cpa_commit();
    };

    const int nsteps = K / 32;
    issue(0); issue(1);

    for (int s = 0; s < nsteps; s++) {
        if (s + 1 < nsteps) cpa_wait<1>();
        else                cpa_wait<0>();
        __syncthreads();
        if (s + 2 < nsteps) issue(s + 2);

        const uint32_t ab = su + (s % GSTAGES) * (A_ST + B_ST);
        const uint32_t bb = ab + A_ST;

        #pragma unroll
        for (int kk = 0; kk < 32; kk += 16) {
            unsigned af[4][4], bf[NTP][4];
            #pragma unroll
            for (int mt = 0; mt < 4; mt++)
                ldsm4(af[mt], ab + (wm + mt * 16 + lrow8) * A_STR
                                 + ((kk >> 3) + lhi) * 16);
            #pragma unroll
            for (int ntp = 0; ntp < NTP; ntp++)
                ldsm4t(bf[ntp], bb + (kk + lrow8) * B_STR
                                   + (((wn + ntp * 16) >> 3) + lhi) * 16);
            #pragma unroll
            for (int mt = 0; mt < 4; mt++)
                #pragma unroll
                for (int ntp = 0; ntp < NTP; ntp++) {
                    mma16(acc[mt][2 * ntp],     af[mt], bf[ntp] + 0);
                    mma16(acc[mt][2 * ntp + 1], af[mt], bf[ntp] + 2);
                }
        }
    }

    #pragma unroll
    for (int mt = 0; mt < 4; mt++) {
        const int row = by * 128 + wm + mt * 16 + g;
        #pragma unroll
        for (int nt = 0; nt < 2 * NTP; nt++) {
            const int col = colb + wn + nt * 8 + tg * 2;
            const float b0 = bias[col], b1 = bias[col + 1];
            float v0 = (acc[mt][nt][0] + b0) * outScale;
            float v1 = (acc[mt][nt][1] + b1) * outScale;
            float v2 = (acc[mt][nt][2] + b0) * outScale;
            float v3 = (acc[mt][nt][3] + b1) * outScale;
            if (Ch) {
                *(unsigned*)(Ch + (size_t)row * N + col)       = packh2(v0, v1);
                *(unsigned*)(Ch + (size_t)(row + 8) * N + col) = packh2(v2, v3);
            } else {
                *(float2*)(Cf + (size_t)row * N + col)       = make_float2(v0, v1);
                *(float2*)(Cf + (size_t)(row + 8) * N + col) = make_float2(v2, v3);
            }
        }
    }
}

#define GEMM_SMEM_QKV (GSTAGES * (A_ST + 32 * 272))   // NT=128: 56832 B
#define GEMM_SMEM_O   (GSTAGES * (A_ST + 32 * 144))   // NT=64:  44544 B

#define QSCALE (0.125f * 1.4426950408889634f)

// Fused QKV projection, 128-wide N tiles: bx 0..15 Wq (scaled), 16..19 Wk, 20..23 Wv
__global__ __launch_bounds__(128, 3)
void gemm_qkv(const __half* __restrict__ x,
              const __half* __restrict__ Wq, const float* __restrict__ bq,
              const __half* __restrict__ Wk, const float* __restrict__ bk,
              const __half* __restrict__ Wv, const float* __restrict__ bv,
              __half* __restrict__ Qo, __half* __restrict__ Ko, __half* __restrict__ Vo)
{
    const int bx = blockIdx.x;
    const __half* B; const float* bias; __half* C; int N, colb; float sc;
    if (bx < 16)      { B = Wq; bias = bq; C = Qo; N = D_MODEL; colb = bx * 128; sc = QSCALE; }
    else if (bx < 20) { B = Wk; bias = bk; C = Ko; N = KV_DIM;  colb = (bx - 16) * 128; sc = 1.f; }
    else              { B = Wv; bias = bv; C = Vo; N = KV_DIM;  colb = (bx - 20) * 128; sc = 1.f; }
    gemm_core<128>(x, B, bias, nullptr, C, N, D_MODEL, colb, blockIdx.y, sc);
}

// Output projection, 64-wide N tiles (wave balance: 1024 CTAs)
__global__ __launch_bounds__(128, 3)
void gemm_o(const __half* __restrict__ A, const __half* __restrict__ B,
            const float* __restrict__ bias, float* __restrict__ C)
{
    gemm_core<64>(A, B, bias, C, nullptr, D_MODEL, D_MODEL, blockIdx.x * 64, blockIdx.y, 1.f);
}

// ---------------------------------------------------------------------------
// Flash attention, fp16 MMA (fp32 accum). 64-query CTAs: 4 warps x 16 rows,
// 128 threads, 3 CTAs/SM. 3-stage KV ring, single barrier per tile;
// P via ex2.approx.f16x2.
// ---------------------------------------------------------------------------
#define KV_STR   144
#define KV_TILE  (64 * KV_STR)               // 9216 B
#define KV_STAGE (2 * KV_TILE)               // 18432 B
#define ASTAGES  3
#define QROWS_A  64
#define Q_OFF    (ASTAGES * KV_STAGE)        // 55296
#define ATTN_SMEM (Q_OFF + QROWS_A * KV_STR) // 64512 B
#define NKT    (SEQ / 64)

__global__ __launch_bounds__(128, 3)
void attn_f16(const __half* __restrict__ Q, const __half* __restrict__ K,
              const __half* __restrict__ V, __half* __restrict__ C)
{
    extern __shared__ char sma[];
    const uint32_t su = (uint32_t)__cvta_generic_to_shared(sma);
    const uint32_t qOff = su + Q_OFF;

    const int tid  = threadIdx.x;
    const int lane = tid & 31;
    const int wid  = tid >> 5;
    const int g    = lane >> 2;
    const int tg   = lane & 3;
    const int r0   = wid * 16;
    const int lrow8 = (lane & 7) + ((lane >> 3) & 1) * 8;
    const int lhi   = lane >> 4;

    const int qt = blockIdx.x;
    const int h  = blockIdx.y;
    const int b  = blockIdx.z;
    const int hkv = h >> 2;

    auto issueKV = [&](int kt) {
        const int st = kt % ASTAGES;
        #pragma unroll
        for (int p = 0; p < 8; p++) {
            int idx = p * 128 + tid;
            int sel = idx >> 9;
            int jj = (idx >> 3) & 63;
            int c  = idx & 7;
            const __half* src = (sel ? V : K)
                + (size_t)(b * SEQ + kt * 64 + jj) * KV_DIM + hkv * HDIM + c * 8;
            cpa16(su + st * KV_STAGE + sel * KV_TILE + jj * KV_STR + c * 16, src);
        }
        cpa_commit();
    };

    // Q tile via cp.async (pre-scaled fp16; 64 rows x 8 chunks)
    {
        #pragma unroll
        for (int p = 0; p < 4; p++) {
            int idx = p * 128 + tid;
            int r = idx >> 3, c = idx & 7;
            cpa16(qOff + r * KV_STR + c * 16,
                  Q + (size_t)(b * SEQ + qt * QROWS_A + r) * D_MODEL + h * HDIM + c * 8);
        }
        cpa_commit();
    }
    issueKV(0); issueKV(1);

    unsigned aQ[4][4];
    float o[8][4];
    #pragma unroll
    for (int nt = 0; nt < 8; nt++)
        #pragma unroll
        for (int i = 0; i < 4; i++) o[nt][i] = 0.f;
    float m0 = -1e30f, m1 = -1e30f, l0 = 0.f, l1 = 0.f;

    for (int kt = 0; kt < NKT; kt++) {
        if (kt + 1 < NKT) cpa_wait<1>();
        else              cpa_wait<0>();
        __syncthreads();
        if (kt + 2 < NKT) issueKV(kt + 2);

        if (kt == 0) {
            #pragma unroll
            for (int kki = 0; kki < 4; kki++)
                ldsm4(aQ[kki], qOff + (r0 + lrow8) * KV_STR + (kki * 2 + lhi) * 16);
        }

        const uint32_t kb = su + (kt % ASTAGES) * KV_STAGE;
        const uint32_t vb = kb + KV_TILE;

        // S = Q @ K^T (log2-scaled, fp32 accum)
        float s[8][4];
        #pragma unroll
        for (int nt = 0; nt < 8; nt++)
            #pragma unroll
            for (int i = 0; i < 4; i++) s[nt][i] = 0.f;

        #pragma unroll
        for (int kki = 0; kki < 4; kki++) {
            #pragma unroll
            for (int ntp = 0; ntp < 4; ntp++) {
                unsigned bK[4];
                ldsm4(bK, kb + (ntp * 16 + (lane & 7) + lhi * 8) * KV_STR
                             + (kki * 2 + ((lane >> 3) & 1)) * 16);
                mma16(s[2 * ntp],     aQ[kki], bK + 0);
                mma16(s[2 * ntp + 1], aQ[kki], bK + 2);
            }
        }

        // Online softmax (exp2 domain, f16x2 MUFU); P kept packed
        unsigned ph[8][2];
        {
            float tm0 = -1e30f, tm1 = -1e30f;
            #pragma unroll
            for (int nt = 0; nt < 8; nt++) {
                tm0 = fmaxf(tm0, fmaxf(s[nt][0], s[nt][1]));
                tm1 = fmaxf(tm1, fmaxf(s[nt][2], s[nt][3]));
            }
            tm0 = fmaxf(tm0, __shfl_xor_sync(0xffffffffu, tm0, 1));
            tm0 = fmaxf(tm0, __shfl_xor_sync(0xffffffffu, tm0, 2));
            tm1 = fmaxf(tm1, __shfl_xor_sync(0xffffffffu, tm1, 1));
            tm1 = fmaxf(tm1, __shfl_xor_sync(0xffffffffu, tm1, 2));

            float nm0 = fmaxf(m0, tm0), nm1 = fmaxf(m1, tm1);
            float c0 = ex2(m0 - nm0), c1 = ex2(m1 - nm1);
            m0 = nm0; m1 = nm1;

            float rs0 = 0.f, rs1 = 0.f;
            #pragma unroll
            for (int nt = 0; nt < 8; nt++) {
                unsigned p01 = ex2h2(packh2(s[nt][0] - nm0, s[nt][1] - nm0));
                unsigned p23 = ex2h2(packh2(s[nt][2] - nm1, s[nt][3] - nm1));
                ph[nt][0] = p01;
                ph[nt][1] = p23;
                float2 f01 = unpackh2(p01);
                float2 f23 = unpackh2(p23);
                rs0 += f01.x + f01.y;
                rs1 += f23.x + f23.y;
                o[nt][0] *= c0; o[nt][1] *= c0;
                o[nt][2] *= c1; o[nt][3] *= c1;
            }
            rs0 += __shfl_xor_sync(0xffffffffu, rs0, 1);
            rs0 += __shfl_xor_sync(0xffffffffu, rs0, 2);
            rs1 += __shfl_xor_sync(0xffffffffu, rs1, 1);
            rs1 += __shfl_xor_sync(0xffffffffu, rs1, 2);
            l0 = l0 * c0 + rs0;
            l1 = l1 * c1 + rs1;
        }

        // O += P @ V (fp32 accum)
        #pragma unroll
        for (int j = 0; j < 4; j++) {
            unsigned aP[4];
            aP[0] = ph[2 * j][0];     aP[1] = ph[2 * j][1];
            aP[2] = ph[2 * j + 1][0]; aP[3] = ph[2 * j + 1][1];
            #pragma unroll
            for (int ntp = 0; ntp < 4; ntp++) {
                unsigned bV[4];
                ldsm4t(bV, vb + (j * 16 + lrow8) * KV_STR + (ntp * 2 + lhi) * 16);
                mma16(o[2 * ntp],     aP, bV + 0);
                mma16(o[2 * ntp + 1], aP, bV + 2);
            }
        }
    }

    // Normalize, write context fp16
    {
        const float i0 = 1.f / l0, i1 = 1.f / l1;
        #pragma unroll
        for (int nt = 0; nt < 8; nt++) {
            const size_t row = (size_t)(b * SEQ + qt * QROWS_A + r0 + g);
            const int col = h * HDIM + nt * 8 + tg * 2;
            *(unsigned*)(C + row * D_MODEL + col) =
                packh2(o[nt][0] * i0, o[nt][1] * i0);
            *(unsigned*)(C + (row + 8) * D_MODEL + col) =
                packh2(o[nt][2] * i1, o[nt][3] * i1);
        }
    }
}

// ---------------------------------------------------------------------------
// Launch
// ---------------------------------------------------------------------------
extern "C" void kernel_launch(void* const* d_in, const int* in_sizes, int n_in,
                              void* d_out, int out_size)
{
    const float* x  = (const float*)d_in[0];
    const float* Wq = (const float*)d_in[1];
    const float* bq = (const float*)d_in[2];
    const float* Wk = (const float*)d_in[3];
    const float* bk = (const float*)d_in[4];
    const float* Wv = (const float*)d_in[5];
    const float* bv = (const float*)d_in[6];
    const float* Wo = (const float*)d_in[7];
    const float* bo = (const float*)d_in[8];
    float* out = (float*)d_out;

    __half *pX, *pWq, *pWk, *pWv, *pWo, *pQ, *pK, *pV, *pC;
    cudaGetSymbolAddress((void**)&pX, g_X);
    cudaGetSymbolAddress((void**)&pWq, g_Wq);
    cudaGetSymbolAddress((void**)&pWk, g_Wk);
    cudaGetSymbolAddress((void**)&pWv, g_Wv);
    cudaGetSymbolAddress((void**)&pWo, g_Wo);
    cudaGetSymbolAddress((void**)&pQ, g_Q);
    cudaGetSymbolAddress((void**)&pK, g_K);
    cudaGetSymbolAddress((void**)&pV, g_V);
    cudaGetSymbolAddress((void**)&pC, g_C);

    cudaFuncSetAttribute(gemm_qkv, cudaFuncAttributeMaxDynamicSharedMemorySize, GEMM_SMEM_QKV);
    cudaFuncSetAttribute(gemm_o,   cudaFuncAttributeMaxDynamicSharedMemorySize, GEMM_SMEM_O);
    cudaFuncSetAttribute(attn_f16, cudaFuncAttributeMaxDynamicSharedMemorySize, ATTN_SMEM);

    // Fused pre-pass: fp32 -> fp16 for all inputs
    cvt_all<<<SEG4 / 256, 256>>>((const float4*)x,  (const float4*)Wq,
                                 (const float4*)Wk, (const float4*)Wv,
                                 (const float4*)Wo,
                                 (uint2*)pX, (uint2*)pWq, (uint2*)pWk,
                                 (uint2*)pWv, (uint2*)pWo);

    // Fused QKV projection: 24 N-tiles (128 wide) x 32 M-tiles
    gemm_qkv<<<dim3(24, MTOK / 128), 128, GEMM_SMEM_QKV>>>(
        pX, pWq, bq, pWk, bk, pWv, bv, pQ, pK, pV);

    // Attention (64-query tiles, 3 CTAs/SM)
    attn_f16<<<dim3(SEQ / QROWS_A, HEADS, BATCH), 128, ATTN_SMEM>>>(pQ, pK, pV, pC);

    // Output projection: 32 N-tiles (64 wide) x 32 M-tiles
    gemm_o<<<dim3(D_MODEL / 64, MTOK / 128), 128, GEMM_SMEM_O>>>(pC, pWo, bo, out);
}

// round 17
// speedup vs baseline: 1.0274x; 1.0266x over previous
#include <cuda_runtime.h>
#include <cuda_fp16.h>
#include <cstdint>

#define D_MODEL 2048
#define KV_DIM  512
#define BATCH   2
#define SEQ     2048
#define MTOK    4096
#define HEADS   32
#define HDIM    64

// Scratch (device globals: no allocations allowed) — fp16 data path
__device__ __half g_X [(size_t)MTOK * D_MODEL];
__device__ __half g_Wq[(size_t)D_MODEL * D_MODEL];
__device__ __half g_Wk[(size_t)D_MODEL * KV_DIM];
__device__ __half g_Wv[(size_t)D_MODEL * KV_DIM];
__device__ __half g_Wo[(size_t)D_MODEL * D_MODEL];
__device__ __half g_Q [(size_t)MTOK * D_MODEL];   // pre-scaled by 0.125*log2e
__device__ __half g_K [(size_t)MTOK * KV_DIM];
__device__ __half g_V [(size_t)MTOK * KV_DIM];
__device__ __half g_C [(size_t)MTOK * D_MODEL];

// ---------------------------------------------------------------------------
// helpers
// ---------------------------------------------------------------------------
__device__ __forceinline__ float ex2(float x) {
    float r;
    asm("ex2.approx.f32 %0, %1;" : "=f"(r) : "f"(x));
    return r;
}
__device__ __forceinline__ unsigned ex2h2(unsigned x) {
    unsigned r;
    asm("ex2.approx.f16x2 %0, %1;" : "=r"(r) : "r"(x));
    return r;
}
__device__ __forceinline__ unsigned packh2(float a, float b) {
    __half2 h = __floats2half2_rn(a, b);
    return *reinterpret_cast<unsigned*>(&h);
}
__device__ __forceinline__ float2 unpackh2(unsigned u) {
    return __half22float2(*reinterpret_cast<__half2*>(&u));
}
__device__ __forceinline__ void mma16(float* d, const unsigned* a, const unsigned* b) {
    asm volatile(
        "mma.sync.aligned.m16n8k16.row.col.f32.f16.f16.f32 "
        "{%0,%1,%2,%3},{%4,%5,%6,%7},{%8,%9},{%0,%1,%2,%3};"
        : "+f"(d[0]), "+f"(d[1]), "+f"(d[2]), "+f"(d[3])
        : "r"(a[0]), "r"(a[1]), "r"(a[2]), "r"(a[3]), "r"(b[0]), "r"(b[1]));
}
__device__ __forceinline__ void ldsm4(unsigned* r, uint32_t a) {
    asm volatile("ldmatrix.sync.aligned.m8n8.x4.shared.b16 {%0,%1,%2,%3}, [%4];"
                 : "=r"(r[0]), "=r"(r[1]), "=r"(r[2]), "=r"(r[3]) : "r"(a));
}
__device__ __forceinline__ void ldsm4t(unsigned* r, uint32_t a) {
    asm volatile("ldmatrix.sync.aligned.m8n8.x4.trans.shared.b16 {%0,%1,%2,%3}, [%4];"
                 : "=r"(r[0]), "=r"(r[1]), "=r"(r[2]), "=r"(r[3]) : "r"(a));
}
__device__ __forceinline__ void cpa16(uint32_t dst, const void* src) {
    asm volatile("cp.async.cg.shared.global [%0], [%1], 16;" :: "r"(dst), "l"(src));
}
__device__ __forceinline__ void cpa_commit() {
    asm volatile("cp.async.commit_group;");
}
template <int N>
__device__ __forceinline__ void cpa_wait() {
    asm volatile("cp.async.wait_group %0;" :: "n"(N));
}

// ---------------------------------------------------------------------------
// Fused pre-pass: fp32 -> fp16 for x + all 4 weights in one launch.
// ---------------------------------------------------------------------------
#define SEG0 (MTOK * D_MODEL / 4)
#define SEG1 (SEG0 + D_MODEL * D_MODEL / 4)
#define SEG2 (SEG1 + D_MODEL * KV_DIM / 4)
#define SEG3 (SEG2 + D_MODEL * KV_DIM / 4)
#define SEG4 (SEG3 + D_MODEL * D_MODEL / 4)

__global__ __launch_bounds__(256)
void cvt_all(const float4* __restrict__ x,  const float4* __restrict__ wq,
             const float4* __restrict__ wk, const float4* __restrict__ wv,
             const float4* __restrict__ wo,
             uint2* __restrict__ ox,  uint2* __restrict__ owq,
             uint2* __restrict__ owk, uint2* __restrict__ owv,
             uint2* __restrict__ owo)
{
    int i = blockIdx.x * 256 + threadIdx.x;
    const float4* src; uint2* dst; int off;
    if (i < SEG0)      { src = x;  dst = ox;  off = i; }
    else if (i < SEG1) { src = wq; dst = owq; off = i - SEG0; }
    else if (i < SEG2) { src = wk; dst = owk; off = i - SEG1; }
    else if (i < SEG3) { src = wv; dst = owv; off = i - SEG2; }
    else               { src = wo; dst = owo; off = i - SEG3; }
    float4 v = src[off];
    uint2 u;
    u.x = packh2(v.x, v.y);
    u.y = packh2(v.z, v.w);
    dst[off] = u;
}

// ---------------------------------------------------------------------------
// fp16 GEMM (fp32 accum): C[M,N] = (A[M,K] @ B[K,N] + bias) * outScale.
// CTA 128x128, K-step 32, 3-stage ring, single barrier per stage,
// 4 warps x (64x64), LDSM operands. (At the mma.sync rt-16 floor.)
// ---------------------------------------------------------------------------
#define A_STR 80
#define B_STR 272
#define A_ST  (128 * A_STR)
#define B_ST  (32 * B_STR)
#define GSTAGES 3
#define GEMM_SMEM (GSTAGES * (A_ST + B_ST))    // 56832 B

__device__ __forceinline__ void gemm_core(
    const __half* __restrict__ A, const __half* __restrict__ B,
    const float* __restrict__ bias, float* __restrict__ Cf, __half* __restrict__ Ch,
    int N, int K, int colb, int by, float outScale)
{
    extern __shared__ char smg[];
    const uint32_t su = (uint32_t)__cvta_generic_to_shared(smg);

    const int tid  = threadIdx.x;
    const int lane = tid & 31;
    const int wid  = tid >> 5;
    const int wm = (wid & 1) * 64;
    const int wn = (wid >> 1) * 64;
    const int g  = lane >> 2;
    const int tg = lane & 3;
    const int lrow8 = (lane & 7) + ((lane >> 3) & 1) * 8;
    const int lhi   = lane >> 4;

    float acc[4][8][4];
    #pragma unroll
    for (int mt = 0; mt < 4; mt++)
        #pragma unroll
        for (int nt = 0; nt < 8; nt++)
            #pragma unroll
            for (int i = 0; i < 4; i++) acc[mt][nt][i] = 0.f;

    auto issue = [&](int stg) {
        const int st = stg % GSTAGES;
        const int k0 = stg * 32;
        const uint32_t ab = su + st * (A_ST + B_ST);
        const uint32_t bb = ab + A_ST;
        #pragma unroll
        for (int p = 0; p < 4; p++) {
            int idx = p * 128 + tid;
            int r = idx >> 2, c = idx & 3;
            cpa16(ab + r * A_STR + c * 16, A + (size_t)(by * 128 + r) * K + k0 + c * 8);
        }
        #pragma unroll
        for (int p = 0; p < 4; p++) {
            int idx = p * 128 + tid;
            int r = idx >> 4, c = idx & 15;
            cpa16(bb + r * B_STR + c * 16, B + (size_t)(k0 + r) * N + colb + c * 8);
        }
        cpa_commit();
    };

    const int nsteps = K / 32;
    issue(0); issue(1);

    for (int s = 0; s < nsteps; s++) {
        if (s + 1 < nsteps) cpa_wait<1>();
        else                cpa_wait<0>();
        __syncthreads();
        if (s + 2 < nsteps) issue(s + 2);

        const uint32_t ab = su + (s % GSTAGES) * (A_ST + B_ST);
        const uint32_t bb = ab + A_ST;

        #pragma unroll
        for (int kk = 0; kk < 32; kk += 16) {
            unsigned af[4][4], bf[4][4];
            #pragma unroll
            for (int mt = 0; mt < 4; mt++)
                ldsm4(af[mt], ab + (wm + mt * 16 + lrow8) * A_STR
                                 + ((kk >> 3) + lhi) * 16);
            #pragma unroll
            for (int ntp = 0; ntp < 4; ntp++)
                ldsm4t(bf[ntp], bb + (kk + lrow8) * B_STR
                                   + (((wn + ntp * 16) >> 3) + lhi) * 16);
            #pragma unroll
            for (int mt = 0; mt < 4; mt++)
                #pragma unroll
                for (int ntp = 0; ntp < 4; ntp++) {
                    mma16(acc[mt][2 * ntp],     af[mt], bf[ntp] + 0);
                    mma16(acc[mt][2 * ntp + 1], af[mt], bf[ntp] + 2);
                }
        }
    }

    #pragma unroll
    for (int mt = 0; mt < 4; mt++) {
        const int row = by * 128 + wm + mt * 16 + g;
        #pragma unroll
        for (int nt = 0; nt < 8; nt++) {
            const int col = colb + wn + nt * 8 + tg * 2;
            const float b0 = bias[col], b1 = bias[col + 1];
            float v0 = (acc[mt][nt][0] + b0) * outScale;
            float v1 = (acc[mt][nt][1] + b1) * outScale;
            float v2 = (acc[mt][nt][2] + b0) * outScale;
            float v3 = (acc[mt][nt][3] + b1) * outScale;
            if (Ch) {
                *(unsigned*)(Ch + (size_t)row * N + col)       = packh2(v0, v1);
                *(unsigned*)(Ch + (size_t)(row + 8) * N + col) = packh2(v2, v3);
            } else {
                *(float2*)(Cf + (size_t)row * N + col)       = make_float2(v0, v1);
                *(float2*)(Cf + (size_t)(row + 8) * N + col) = make_float2(v2, v3);
            }
        }
    }
}

#define QSCALE (0.125f * 1.4426950408889634f)

// Fused QKV projection: bx 0..15 -> Wq (scaled), 16..19 -> Wk, 20..23 -> Wv
__global__ __launch_bounds__(128, 3)
void gemm_qkv(const __half* __restrict__ x,
              const __half* __restrict__ Wq, const float* __restrict__ bq,
              const __half* __restrict__ Wk, const float* __restrict__ bk,
              const __half* __restrict__ Wv, const float* __restrict__ bv,
              __half* __restrict__ Qo, __half* __restrict__ Ko, __half* __restrict__ Vo)
{
    const int bx = blockIdx.x;
    const __half* B; const float* bias; __half* C; int N, colb; float sc;
    if (bx < 16)      { B = Wq; bias = bq; C = Qo; N = D_MODEL; colb = bx * 128; sc = QSCALE; }
    else if (bx < 20) { B = Wk; bias = bk; C = Ko; N = KV_DIM;  colb = (bx - 16) * 128; sc = 1.f; }
    else              { B = Wv; bias = bv; C = Vo; N = KV_DIM;  colb = (bx - 20) * 128; sc = 1.f; }
    gemm_core(x, B, bias, nullptr, C, N, D_MODEL, colb, blockIdx.y, sc);
}

__global__ __launch_bounds__(128, 3)
void gemm_o(const __half* __restrict__ A, const __half* __restrict__ B,
            const float* __restrict__ bias, float* __restrict__ C)
{
    gemm_core(A, B, bias, C, nullptr, D_MODEL, D_MODEL, blockIdx.x * 128, blockIdx.y, 1.f);
}

// ---------------------------------------------------------------------------
// Flash attention, fp16 MMA (fp32 accum). 64-query CTAs: 4 warps x 16 rows,
// 128 threads, 3 CTAs/SM (fine-grained tiles kill the wave tail).
// 3-stage KV ring, single barrier per tile; P via ex2.approx.f16x2.
// ---------------------------------------------------------------------------
#define KV_STR   144
#define KV_TILE  (64 * KV_STR)               // 9216 B
#define KV_STAGE (2 * KV_TILE)               // 18432 B
#define ASTAGES  3
#define QROWS_A  64
#define Q_OFF    (ASTAGES * KV_STAGE)        // 55296
#define ATTN_SMEM (Q_OFF + QROWS_A * KV_STR) // 64512 B
#define NKT    (SEQ / 64)

__global__ __launch_bounds__(128, 3)
void attn_f16(const __half* __restrict__ Q, const __half* __restrict__ K,
              const __half* __restrict__ V, __half* __restrict__ C)
{
    extern __shared__ char sma[];
    const uint32_t su = (uint32_t)__cvta_generic_to_shared(sma);
    const uint32_t qOff = su + Q_OFF;

    const int tid  = threadIdx.x;
    const int lane = tid & 31;
    const int wid  = tid >> 5;          // 0..3
    const int g    = lane >> 2;
    const int tg   = lane & 3;
    const int r0   = wid * 16;          // warp's 16 query rows
    const int lrow8 = (lane & 7) + ((lane >> 3) & 1) * 8;
    const int lhi   = lane >> 4;

    const int qt = blockIdx.x;          // 64-query tile
    const int h  = blockIdx.y;
    const int b  = blockIdx.z;
    const int hkv = h >> 2;

    auto issueKV = [&](int kt) {
        const int st = kt % ASTAGES;
        #pragma unroll
        for (int p = 0; p < 8; p++) {   // 1024 16B chunks (K 512 + V 512)
            int idx = p * 128 + tid;
            int sel = idx >> 9;
            int jj = (idx >> 3) & 63;
            int c  = idx & 7;
            const __half* src = (sel ? V : K)
                + (size_t)(b * SEQ + kt * 64 + jj) * KV_DIM + hkv * HDIM + c * 8;
            cpa16(su + st * KV_STAGE + sel * KV_TILE + jj * KV_STR + c * 16, src);
        }
        cpa_commit();
    };

    // Q tile via cp.async (pre-scaled fp16; 64 rows x 8 chunks)
    {
        #pragma unroll
        for (int p = 0; p < 4; p++) {
            int idx = p * 128 + tid;
            int r = idx >> 3, c = idx & 7;
            cpa16(qOff + r * KV_STR + c * 16,
                  Q + (size_t)(b * SEQ + qt * QROWS_A + r) * D_MODEL + h * HDIM + c * 8);
        }
        cpa_commit();
    }
    issueKV(0); issueKV(1);

    unsigned aQ[4][4];
    float o[8][4];
    #pragma unroll
    for (int nt = 0; nt < 8; nt++)
        #pragma unroll
        for (int i = 0; i < 4; i++) o[nt][i] = 0.f;
    float m0 = -1e30f, m1 = -1e30f, l0 = 0.f, l1 = 0.f;

    for (int kt = 0; kt < NKT; kt++) {
        if (kt + 1 < NKT) cpa_wait<1>();
        else              cpa_wait<0>();
        __syncthreads();
        if (kt + 2 < NKT) issueKV(kt + 2);

        if (kt == 0) {
            #pragma unroll
            for (int kki = 0; kki < 4; kki++)
                ldsm4(aQ[kki], qOff + (r0 + lrow8) * KV_STR + (kki * 2 + lhi) * 16);
        }

        const uint32_t kb = su + (kt % ASTAGES) * KV_STAGE;
        const uint32_t vb = kb + KV_TILE;

        // S = Q @ K^T (log2-scaled, fp32 accum)
        float s[8][4];
        #pragma unroll
        for (int nt = 0; nt < 8; nt++)
            #pragma unroll
            for (int i = 0; i < 4; i++) s[nt][i] = 0.f;

        #pragma unroll
        for (int kki = 0; kki < 4; kki++) {
            #pragma unroll
            for (int ntp = 0; ntp < 4; ntp++) {
                unsigned bK[4];
                ldsm4(bK, kb + (ntp * 16 + (lane & 7) + lhi * 8) * KV_STR
                             + (kki * 2 + ((lane >> 3) & 1)) * 16);
                mma16(s[2 * ntp],     aQ[kki], bK + 0);
                mma16(s[2 * ntp + 1], aQ[kki], bK + 2);
            }
        }

        // Online softmax (exp2 domain, f16x2 MUFU); P kept packed
        unsigned ph[8][2];
        {
            float tm0 = -1e30f, tm1 = -1e30f;
            #pragma unroll
            for (int nt = 0; nt < 8; nt++) {
                tm0 = fmaxf(tm0, fmaxf(s[nt][0], s[nt][1]));
                tm1 = fmaxf(tm1, fmaxf(s[nt][2], s[nt][3]));
            }
            tm0 = fmaxf(tm0, __shfl_xor_sync(0xffffffffu, tm0, 1));
            tm0 = fmaxf(tm0, __shfl_xor_sync(0xffffffffu, tm0, 2));
            tm1 = fmaxf(tm1, __shfl_xor_sync(0xffffffffu, tm1, 1));
            tm1 = fmaxf(tm1, __shfl_xor_sync(0xffffffffu, tm1, 2));

            float nm0 = fmaxf(m0, tm0), nm1 = fmaxf(m1, tm1);
            float c0 = ex2(m0 - nm0), c1 = ex2(m1 - nm1);
            m0 = nm0; m1 = nm1;

            float rs0 = 0.f, rs1 = 0.f;
            #pragma unroll
            for (int nt = 0; nt < 8; nt++) {
                unsigned p01 = ex2h2(packh2(s[nt][0] - nm0, s[nt][1] - nm0));
                unsigned p23 = ex2h2(packh2(s[nt][2] - nm1, s[nt][3] - nm1));
                ph[nt][0] = p01;
                ph[nt][1] = p23;
                float2 f01 = unpackh2(p01);
                float2 f23 = unpackh2(p23);
                rs0 += f01.x + f01.y;
                rs1 += f23.x + f23.y;
                o[nt][0] *= c0; o[nt][1] *= c0;
                o[nt][2] *= c1; o[nt][3] *= c1;
            }
            rs0 += __shfl_xor_sync(0xffffffffu, rs0, 1);
            rs0 += __shfl_xor_sync(0xffffffffu, rs0, 2);
            rs1 += __shfl_xor_sync(0xffffffffu, rs1, 1);
            rs1 += __shfl_xor_sync(0xffffffffu, rs1, 2);
            l0 = l0 * c0 + rs0;
            l1 = l1 * c1 + rs1;
        }

        // O += P @ V (fp32 accum)
        #pragma unroll
        for (int j = 0; j < 4; j++) {
            unsigned aP[4];
            aP[0] = ph[2 * j][0];     aP[1] = ph[2 * j][1];
            aP[2] = ph[2 * j + 1][0]; aP[3] = ph[2 * j + 1][1];
            #pragma unroll
            for (int ntp = 0; ntp < 4; ntp++) {
                unsigned bV[4];
                ldsm4t(bV, vb + (j * 16 + lrow8) * KV_STR + (ntp * 2 + lhi) * 16);
                mma16(o[2 * ntp],     aP, bV + 0);
                mma16(o[2 * ntp + 1], aP, bV + 2);
            }
        }
    }

    // Normalize, write context fp16
    {
        const float i0 = 1.f / l0, i1 = 1.f / l1;
        #pragma unroll
        for (int nt = 0; nt < 8; nt++) {
            const size_t row = (size_t)(b * SEQ + qt * QROWS_A + r0 + g);
            const int col = h * HDIM + nt * 8 + tg * 2;
            *(unsigned*)(C + row * D_MODEL + col) =
                packh2(o[nt][0] * i0, o[nt][1] * i0);
            *(unsigned*)(C + (row + 8) * D_MODEL + col) =
                packh2(o[nt][2] * i1, o[nt][3] * i1);
        }
    }
}

// ---------------------------------------------------------------------------
// Launch
// ---------------------------------------------------------------------------
extern "C" void kernel_launch(void* const* d_in, const int* in_sizes, int n_in,
                              void* d_out, int out_size)
{
    const float* x  = (const float*)d_in[0];
    const float* Wq = (const float*)d_in[1];
    const float* bq = (const float*)d_in[2];
    const float* Wk = (const float*)d_in[3];
    const float* bk = (const float*)d_in[4];
    const float* Wv = (const float*)d_in[5];
    const float* bv = (const float*)d_in[6];
    const float* Wo = (const float*)d_in[7];
    const float* bo = (const float*)d_in[8];
    float* out = (float*)d_out;

    __half *pX, *pWq, *pWk, *pWv, *pWo, *pQ, *pK, *pV, *pC;
    cudaGetSymbolAddress((void**)&pX, g_X);
    cudaGetSymbolAddress((void**)&pWq, g_Wq);
    cudaGetSymbolAddress((void**)&pWk, g_Wk);
    cudaGetSymbolAddress((void**)&pWv, g_Wv);
    cudaGetSymbolAddress((void**)&pWo, g_Wo);
    cudaGetSymbolAddress((void**)&pQ, g_Q);
    cudaGetSymbolAddress((void**)&pK, g_K);
    cudaGetSymbolAddress((void**)&pV, g_V);
    cudaGetSymbolAddress((void**)&pC, g_C);

    cudaFuncSetAttribute(gemm_qkv, cudaFuncAttributeMaxDynamicSharedMemorySize, GEMM_SMEM);
    cudaFuncSetAttribute(gemm_o,   cudaFuncAttributeMaxDynamicSharedMemorySize, GEMM_SMEM);
    cudaFuncSetAttribute(attn_f16, cudaFuncAttributeMaxDynamicSharedMemorySize, ATTN_SMEM);

    // Fused pre-pass: fp32 -> fp16 for all inputs
    cvt_all<<<SEG4 / 256, 256>>>((const float4*)x,  (const float4*)Wq,
                                 (const float4*)Wk, (const float4*)Wv,
                                 (const float4*)Wo,
                                 (uint2*)pX, (uint2*)pWq, (uint2*)pWk,
                                 (uint2*)pWv, (uint2*)pWo);

    // Fused QKV projection (fp16 outputs; Q pre-scaled)
    gemm_qkv<<<dim3(24, MTOK / 128), 128, GEMM_SMEM>>>(
        pX, pWq, bq, pWk, bk, pWv, bv, pQ, pK, pV);

    // Attention (64-query tiles, 3 CTAs/SM)
    attn_f16<<<dim3(SEQ / QROWS_A, HEADS, BATCH), 128, ATTN_SMEM>>>(pQ, pK, pV, pC);

    // Output projection (fp32 output)
    gemm_o<<<dim3(D_MODEL / 128, MTOK / 128), 128, GEMM_SMEM>>>(pC, pWo, bo, out);
}